// round 1
// baseline (speedup 1.0000x reference)
#include <cuda_runtime.h>
#include <math.h>

#define EPSF 1e-5f

// ---------------- scratch arena (single __device__ global, ~100MB) ----------------
// offsets (floats):
// h1   : 0         (384*32*32*16 = 6291456)
// h2   : 6291456   (384*16*16*32 = 3145728)
// h3   : 9437184   (384*4096     = 1572864)
// hf   : 11010048  (384*512)
// s1   : 11206656  (384*250)
// A    : 11302656  (384*250)
// B    : 11398656  (384*250)
// core : 11494656  (2688*250)
// ctx  : 12166656  (2688*250)
// att1 : 12838656  (2688*100)
// att  : 13107456  (2688)
// eff  : 13110144  (384*250)
// tot  : 13206144  (384*1012)
// ns   : 13594752  (384*250)
// xr   : 13690752  (384*250)
// d1   : 13786752  (384*512)
// d2   : 13983360  (384*4096)
// dd1  : 15556224  (384*16*16*32)
// dd2  : 18701952  (384*32*32*16)
// end  : 24993408
__device__ float g_scratch[24993408];

// ---------------- block reductions (blockDim.x == 256 everywhere) ----------------
__device__ __forceinline__ void reduce2(float& s, float& s2) {
    __shared__ float rA[256];
    __shared__ float rB[256];
    __syncthreads();                 // protect re-use of rA/rB across calls
    int t = threadIdx.x;
    rA[t] = s; rB[t] = s2;
    __syncthreads();
    for (int off = 128; off > 0; off >>= 1) {
        if (t < off) { rA[t] += rA[t + off]; rB[t] += rB[t + off]; }
        __syncthreads();
    }
    s = rA[0]; s2 = rB[0];
}

// ---------------- encoder conv (stride2, pad1, k4) + ln_all + ELU, one CTA/sample ----------------
// out[n,a,b,o] = sum_{i,kh,kw} in[n, 2a-1+kw, 2b-1+kh, i] * w[o,i,kh,kw] + bias[o]
template<int S_IN, int C_IN, int C_OUT>
__global__ void k_conv_ln_elu(const float* __restrict__ in, const float* __restrict__ w,
                              const float* __restrict__ bias, float* __restrict__ out) {
    constexpr int S_OUT = S_IN / 2;
    constexpr int NIN   = S_IN * S_IN * C_IN;
    constexpr int NW    = C_OUT * C_IN * 16;
    constexpr int NOUT  = S_OUT * S_OUT * C_OUT;
    constexpr int VEC   = (C_OUT % 4 == 0) ? 4 : 1;
    constexpr int OG    = C_OUT / VEC;
    extern __shared__ float sm[];
    float* xs = sm;                 // NIN
    float* ws = sm + NIN;           // NW, layout [(i*16 + kh*4 + kw)*C_OUT + o]
    float* bs = ws + NW;            // C_OUT
    int n = blockIdx.x, t = threadIdx.x;
    const float* inp = in + (size_t)n * NIN;
    for (int idx = t; idx < NIN; idx += 256) xs[idx] = inp[idx];
    for (int idx = t; idx < NW; idx += 256) {
        int o = idx / (C_IN * 16); int rem = idx % (C_IN * 16);
        ws[rem * C_OUT + o] = w[idx];
    }
    for (int idx = t; idx < C_OUT; idx += 256) bs[idx] = bias[idx];
    __syncthreads();

    float s = 0.f, s2 = 0.f;
    float* op = out + (size_t)n * NOUT;
    for (int it = t; it < NOUT / VEC; it += 256) {
        int og = it % OG; int ab = it / OG;
        int b = ab % S_OUT, a = ab / S_OUT;
        int o = og * VEC;
        float acc[VEC];
        #pragma unroll
        for (int v = 0; v < VEC; v++) acc[v] = bs[o + v];
        #pragma unroll
        for (int kw = 0; kw < 4; kw++) {
            int u = 2 * a - 1 + kw; if (u < 0 || u >= S_IN) continue;
            #pragma unroll
            for (int kh = 0; kh < 4; kh++) {
                int vv = 2 * b - 1 + kh; if (vv < 0 || vv >= S_IN) continue;
                const float* xb = &xs[(u * S_IN + vv) * C_IN];
                const float* wb = &ws[(kh * 4 + kw) * C_OUT + o];
                for (int i = 0; i < C_IN; i++) {
                    float xv = xb[i];
                    if constexpr (VEC == 4) {
                        float4 wv = *reinterpret_cast<const float4*>(wb + i * 16 * C_OUT);
                        acc[0] += xv * wv.x; acc[1] += xv * wv.y;
                        acc[2] += xv * wv.z; acc[3] += xv * wv.w;
                    } else {
                        acc[0] += xv * wb[i * 16 * C_OUT];
                    }
                }
            }
        }
        int base = ab * C_OUT + o;
        #pragma unroll
        for (int v = 0; v < VEC; v++) { float z = acc[v]; op[base + v] = z; s += z; s2 += z * z; }
    }
    reduce2(s, s2);
    float mean = s / NOUT;
    float var  = s2 / NOUT - mean * mean;
    float rsg  = rsqrtf(var + EPSF);
    for (int idx = t; idx < NOUT; idx += 256) {
        float v = (op[idx] - mean) * rsg;
        op[idx] = v > 0.f ? v : expm1f(v);
    }
}

// ---------------- decoder: up4 + conv(stride2,pad1,k4), with 4x FLOP reduction ----------------
// Upsampled window of 4 spans <=2 distinct source pixels per axis; aggregate taps per
// (parity, group). W2[pa][pb][ga][gb][i][o] = sum of w[o,i,kh,kw] over the tap group.
// ACT==0: ln_all + ReLU (in-place on out). ACT==1: sigmoid (final output, C_OUT==1).
template<int S_IN, int C_IN, int C_OUT, int ACT>
__global__ void k_deconv(const float* __restrict__ in, const float* __restrict__ w,
                         const float* __restrict__ bias, float* __restrict__ out) {
    constexpr int S_OUT = 2 * S_IN;
    constexpr int NIN   = S_IN * S_IN * C_IN;
    constexpr int NW2   = 16 * C_IN * C_OUT;
    constexpr int NOUT  = S_OUT * S_OUT * C_OUT;
    constexpr int VEC   = (C_OUT % 4 == 0) ? 4 : 1;
    constexpr int OG    = C_OUT / VEC;
    extern __shared__ float sm[];
    float* xs = sm;            // NIN
    float* w2 = sm + NIN;      // NW2, layout [g*C_IN*C_OUT + i*C_OUT + o], g=((pa*2+pb)*2+ga)*2+gb
    float* bs = w2 + NW2;      // C_OUT
    int n = blockIdx.x, t = threadIdx.x;
    const float* inp = in + (size_t)n * NIN;
    for (int idx = t; idx < NIN; idx += 256) xs[idx] = inp[idx];
    for (int idx = t; idx < NW2; idx += 256) {
        int o = idx % C_OUT; int rem = idx / C_OUT;
        int i = rem % C_IN;  int g = rem / C_IN;
        int gb = g & 1, ga = (g >> 1) & 1, pb = (g >> 2) & 1, pa = (g >> 3) & 1;
        int kw0, kw1, kh0, kh1;
        if (pa == 0) { if (ga == 0) { kw0 = 0; kw1 = 1; } else { kw0 = 1; kw1 = 4; } }
        else         { if (ga == 0) { kw0 = 0; kw1 = 3; } else { kw0 = 3; kw1 = 4; } }
        if (pb == 0) { if (gb == 0) { kh0 = 0; kh1 = 1; } else { kh0 = 1; kh1 = 4; } }
        else         { if (gb == 0) { kh0 = 0; kh1 = 3; } else { kh0 = 3; kh1 = 4; } }
        float sum = 0.f;
        for (int kw = kw0; kw < kw1; kw++)
            for (int kh = kh0; kh < kh1; kh++)
                sum += w[((o * C_IN + i) * 4 + kh) * 4 + kw];
        w2[(g * C_IN + i) * C_OUT + o] = sum;
    }
    for (int idx = t; idx < C_OUT; idx += 256) bs[idx] = bias[idx];
    __syncthreads();

    float s = 0.f, s2 = 0.f;
    float* op = out + (size_t)n * NOUT;
    for (int it = t; it < NOUT / VEC; it += 256) {
        int og = it % OG; int ab = it / OG;
        int b = ab % S_OUT, a = ab / S_OUT;
        int o = og * VEC;
        int pa = a & 1, ma = a >> 1, pb = b & 1, mb = b >> 1;
        int sua0 = pa ? ma     : ma - 1;
        int sua1 = pa ? ma + 1 : ma;
        int svb0 = pb ? mb     : mb - 1;
        int svb1 = pb ? mb + 1 : mb;
        float acc[VEC];
        #pragma unroll
        for (int v = 0; v < VEC; v++) acc[v] = bs[o + v];
        #pragma unroll
        for (int ga = 0; ga < 2; ga++) {
            int su = ga ? sua1 : sua0; if (su < 0 || su >= S_IN) continue;
            #pragma unroll
            for (int gb = 0; gb < 2; gb++) {
                int sv = gb ? svb1 : svb0; if (sv < 0 || sv >= S_IN) continue;
                const float* xb = &xs[(su * S_IN + sv) * C_IN];
                const float* wb = &w2[((((pa * 2 + pb) * 2 + ga) * 2 + gb) * C_IN) * C_OUT + o];
                for (int i = 0; i < C_IN; i++) {
                    float xv = xb[i];
                    if constexpr (VEC == 4) {
                        float4 wv = *reinterpret_cast<const float4*>(wb + i * C_OUT);
                        acc[0] += xv * wv.x; acc[1] += xv * wv.y;
                        acc[2] += xv * wv.z; acc[3] += xv * wv.w;
                    } else {
                        acc[0] += xv * wb[i * C_OUT];
                    }
                }
            }
        }
        int base = ab * C_OUT + o;
        if (ACT == 1) {
            #pragma unroll
            for (int v = 0; v < VEC; v++) op[base + v] = 1.f / (1.f + expf(-acc[v]));
        } else {
            #pragma unroll
            for (int v = 0; v < VEC; v++) { float z = acc[v]; op[base + v] = z; s += z; s2 += z * z; }
        }
    }
    if (ACT == 0) {
        reduce2(s, s2);
        float mean = s / NOUT;
        float var  = s2 / NOUT - mean * mean;
        float rsg  = rsqrtf(var + EPSF);
        for (int idx = t; idx < NOUT; idx += 256) {
            float v = (op[idx] - mean) * rsg;
            op[idx] = v > 0.f ? v : 0.f;
        }
    }
}

// ---------------- generic tiled GEMM: C[M,N] = A[M,K] @ B[K,N] + bias ----------------
__global__ void k_gemm(const float* __restrict__ A, const float* __restrict__ B,
                       const float* __restrict__ bias, float* __restrict__ C,
                       int M, int N, int K) {
    __shared__ float As[16][65];
    __shared__ float Bs[16][64];
    int tx = threadIdx.x % 16, ty = threadIdx.x / 16;
    int m0 = blockIdx.y * 64, n0 = blockIdx.x * 64;
    float acc[4][4] = {};
    for (int k0 = 0; k0 < K; k0 += 16) {
        for (int idx = threadIdx.x; idx < 1024; idx += 256) {
            int r = idx >> 4, c = idx & 15;
            int m = m0 + r, k = k0 + c;
            As[c][r] = (m < M && k < K) ? A[(size_t)m * K + k] : 0.f;
            int r2 = idx >> 6, c2 = idx & 63;
            int k2 = k0 + r2, nn = n0 + c2;
            Bs[r2][c2] = (k2 < K && nn < N) ? B[(size_t)k2 * N + nn] : 0.f;
        }
        __syncthreads();
        #pragma unroll
        for (int k = 0; k < 16; k++) {
            float av[4], bv[4];
            #pragma unroll
            for (int i = 0; i < 4; i++) av[i] = As[k][ty + 16 * i];
            #pragma unroll
            for (int j = 0; j < 4; j++) bv[j] = Bs[k][tx + 16 * j];
            #pragma unroll
            for (int i = 0; i < 4; i++)
                #pragma unroll
                for (int j = 0; j < 4; j++) acc[i][j] += av[i] * bv[j];
        }
        __syncthreads();
    }
    for (int i = 0; i < 4; i++) {
        int m = m0 + ty + 16 * i; if (m >= M) continue;
        for (int j = 0; j < 4; j++) {
            int nn = n0 + tx + 16 * j; if (nn >= N) continue;
            C[(size_t)m * N + nn] = acc[i][j] + (bias ? bias[nn] : 0.f);
        }
    }
}

// ---------------- per-row layernorm (last axis) + activation, in-place ----------------
// act: 0 = ELU, 1 = ReLU
__global__ void k_ln_act(float* __restrict__ X, int N, int act) {
    int r = blockIdx.x;
    float* x = X + (size_t)r * N;
    float s = 0.f, s2 = 0.f;
    for (int c = threadIdx.x; c < N; c += 256) { float v = x[c]; s += v; s2 += v * v; }
    reduce2(s, s2);
    float mean = s / N, var = s2 / N - mean * mean, rsg = rsqrtf(var + EPSF);
    for (int c = threadIdx.x; c < N; c += 256) {
        float v = (x[c] - mean) * rsg;
        x[c] = (act == 0) ? (v > 0.f ? v : expm1f(v)) : (v > 0.f ? v : 0.f);
    }
}

// ---------------- core rows: relu(ln( A[fi] + B[bi*8+j] + bias )) ----------------
__global__ void k_core(const float* __restrict__ A, const float* __restrict__ Bm,
                       const float* __restrict__ bias, float* __restrict__ core) {
    int r = blockIdx.x;                  // r = (bi*8+i)*7 + jj
    int jj = r % 7; int fi = r / 7; int i = fi % 8; int bi = fi / 8;
    int j = (jj < i) ? jj : jj + 1;
    const float* ar = A  + (size_t)fi * 250;
    const float* br = Bm + (size_t)(bi * 8 + j) * 250;
    __shared__ float row[256];
    float s = 0.f, s2 = 0.f;
    for (int c = threadIdx.x; c < 250; c += 256) {
        float v = ar[c] + br[c] + bias[c];
        row[c] = v; s += v; s2 += v * v;
    }
    reduce2(s, s2);
    float mean = s / 250.f, var = s2 / 250.f - mean * mean, rsg = rsqrtf(var + EPSF);
    float* o = core + (size_t)r * 250;
    for (int c = threadIdx.x; c < 250; c += 256) {
        float v = (row[c] - mean) * rsg;
        o[c] = v > 0.f ? v : 0.f;
    }
}

// ---------------- att: sigmoid( tanh(ln(att1_row)) . att2_w + att2_b ) ----------------
__global__ void k_att(const float* __restrict__ X, const float* __restrict__ w2,
                      const float* __restrict__ b2, float* __restrict__ att) {
    int r = blockIdx.x;
    const float* x = X + (size_t)r * 100;
    float s = 0.f, s2 = 0.f;
    for (int c = threadIdx.x; c < 100; c += 256) { float v = x[c]; s += v; s2 += v * v; }
    reduce2(s, s2);
    float mean = s / 100.f, var = s2 / 100.f - mean * mean, rsg = rsqrtf(var + EPSF);
    float d = 0.f;
    for (int c = threadIdx.x; c < 100; c += 256) {
        float v = tanhf((x[c] - mean) * rsg);
        d += v * w2[c];
    }
    float dummy = 0.f;
    reduce2(d, dummy);
    if (threadIdx.x == 0) att[r] = 1.f / (1.f + expf(-(d + b2[0])));
}

// ---------------- effect[fi, c] = sum_jj ctx[fi*7+jj, c] * att[fi*7+jj] ----------------
__global__ void k_eff(const float* __restrict__ ctx, const float* __restrict__ att,
                      float* __restrict__ eff) {
    int idx = blockIdx.x * 256 + threadIdx.x;
    if (idx >= 384 * 250) return;
    int c = idx % 250; int fi = idx / 250;
    float s = 0.f;
    #pragma unroll
    for (int jj = 0; jj < 7; jj++)
        s += ctx[((size_t)fi * 7 + jj) * 250 + c] * att[fi * 7 + jj];
    eff[idx] = s;
}

// ---------------- total = concat([s1, effect, h], axis=1) ----------------
__global__ void k_total(const float* __restrict__ s1, const float* __restrict__ eff,
                        const float* __restrict__ h, float* __restrict__ total) {
    int idx = blockIdx.x * 256 + threadIdx.x;
    if (idx >= 384 * 1012) return;
    int n = idx / 1012, c = idx % 1012;
    float v = (c < 250) ? s1[n * 250 + c]
            : (c < 500) ? eff[n * 250 + (c - 250)]
                        : h[n * 512 + (c - 500)];
    total[idx] = v;
}

// ---------------- xr = sigmoid(ln(ns)); state_out = sigmoid(ns) ----------------
__global__ void k_state(const float* __restrict__ ns, float* __restrict__ xr,
                        float* __restrict__ so) {
    int r = blockIdx.x;
    const float* x = ns + (size_t)r * 250;
    float s = 0.f, s2 = 0.f;
    for (int c = threadIdx.x; c < 250; c += 256) { float v = x[c]; s += v; s2 += v * v; }
    reduce2(s, s2);
    float mean = s / 250.f, var = s2 / 250.f - mean * mean, rsg = rsqrtf(var + EPSF);
    for (int c = threadIdx.x; c < 250; c += 256) {
        float v = x[c];
        xr[(size_t)r * 250 + c] = 1.f / (1.f + expf(-((v - mean) * rsg)));
        so[(size_t)r * 250 + c] = 1.f / (1.f + expf(-v));
    }
}

// ---------------- launch ----------------
extern "C" void kernel_launch(void* const* d_in, const int* in_sizes, int n_in,
                              void* d_out, int out_size) {
    const float* x     = (const float*)d_in[0];
    const float* state = (const float*)d_in[1];
    const float* c1w   = (const float*)d_in[2];  const float* c1b  = (const float*)d_in[3];
    const float* c2w   = (const float*)d_in[4];  const float* c2b  = (const float*)d_in[5];
    const float* c3w   = (const float*)d_in[6];  const float* c3b  = (const float*)d_in[7];
    const float* efcw  = (const float*)d_in[8];  const float* efcb = (const float*)d_in[9];
    const float* rencw = (const float*)d_in[10]; const float* rencb= (const float*)d_in[11];
    const float* corew = (const float*)d_in[12]; const float* coreb= (const float*)d_in[13];
    const float* ctxw  = (const float*)d_in[14]; const float* ctxb = (const float*)d_in[15];
    const float* att1w = (const float*)d_in[16]; const float* att1b= (const float*)d_in[17];
    const float* att2w = (const float*)d_in[18]; const float* att2b= (const float*)d_in[19];
    const float* outw  = (const float*)d_in[20]; const float* outb = (const float*)d_in[21];
    const float* dfc1w = (const float*)d_in[22]; const float* dfc1b= (const float*)d_in[23];
    const float* dfc2w = (const float*)d_in[24]; const float* dfc2b= (const float*)d_in[25];
    const float* d1w   = (const float*)d_in[26]; const float* d1b  = (const float*)d_in[27];
    const float* d2w   = (const float*)d_in[28]; const float* d2b  = (const float*)d_in[29];
    const float* d3w   = (const float*)d_in[30]; const float* d3b  = (const float*)d_in[31];
    float* out = (float*)d_out;

    float* S = nullptr;
    cudaGetSymbolAddress((void**)&S, g_scratch);
    float* h1   = S;
    float* h2   = h1 + 6291456;
    float* h3   = h2 + 3145728;
    float* hf   = h3 + 1572864;
    float* s1   = hf + 196608;
    float* Aa   = s1 + 96000;
    float* Bb   = Aa + 96000;
    float* core = Bb + 96000;
    float* ctx  = core + 672000;
    float* att1 = ctx + 672000;
    float* att  = att1 + 268800;
    float* eff  = att + 2688;
    float* tot  = eff + 96000;
    float* ns   = tot + 388608;
    float* xr   = ns + 96000;
    float* d1   = xr + 96000;
    float* d2   = d1 + 196608;
    float* dd1  = d2 + 1572864;
    float* dd2  = dd1 + 3145728;

    // opt-in dynamic smem for the big kernels (idempotent; not a stream op)
    cudaFuncSetAttribute(k_conv_ln_elu<32,16,32>, cudaFuncAttributeMaxDynamicSharedMemorySize, (16384+8192+32)*4);
    cudaFuncSetAttribute(k_conv_ln_elu<16,32,64>, cudaFuncAttributeMaxDynamicSharedMemorySize, (8192+32768+64)*4);
    cudaFuncSetAttribute(k_deconv<8,64,32,0>,     cudaFuncAttributeMaxDynamicSharedMemorySize, (4096+32768+32)*4);
    cudaFuncSetAttribute(k_deconv<16,32,16,0>,    cudaFuncAttributeMaxDynamicSharedMemorySize, (8192+8192+16)*4);
    cudaFuncSetAttribute(k_deconv<32,16,1,1>,     cudaFuncAttributeMaxDynamicSharedMemorySize, (16384+256+1)*4);

    // ---- encoder ----
    k_conv_ln_elu<64,1,16><<<384, 256, (4096+256+16)*4>>>(x, c1w, c1b, h1);
    k_conv_ln_elu<32,16,32><<<384, 256, (16384+8192+32)*4>>>(h1, c2w, c2b, h2);
    k_conv_ln_elu<16,32,64><<<384, 256, (8192+32768+64)*4>>>(h2, c3w, c3b, h3);
    { dim3 g(8, 6);  k_gemm<<<g, 256>>>(h3, efcw, efcb, hf, 384, 512, 4096); }
    k_ln_act<<<384, 256>>>(hf, 512, 0);                       // ELU

    // ---- recurrent / pairwise ----
    { dim3 g(4, 6);  k_gemm<<<g, 256>>>(state, rencw, rencb, s1, 384, 250, 250); }
    k_ln_act<<<384, 256>>>(s1, 250, 1);                       // ReLU
    { dim3 g(4, 6);  k_gemm<<<g, 256>>>(s1, corew,          (const float*)nullptr, Aa, 384, 250, 250); }
    { dim3 g(4, 6);  k_gemm<<<g, 256>>>(s1, corew + 62500,  (const float*)nullptr, Bb, 384, 250, 250); }
    k_core<<<2688, 256>>>(Aa, Bb, coreb, core);
    { dim3 g(4, 42); k_gemm<<<g, 256>>>(core, ctxw, ctxb, ctx, 2688, 250, 250); }
    k_ln_act<<<2688, 256>>>(ctx, 250, 1);                     // ReLU
    { dim3 g(2, 42); k_gemm<<<g, 256>>>(core, att1w, att1b, att1, 2688, 100, 250); }
    k_att<<<2688, 256>>>(att1, att2w, att2b, att);
    k_eff<<<(96000 + 255) / 256, 256>>>(ctx, att, eff);
    k_total<<<(388608 + 255) / 256, 256>>>(s1, eff, hf, tot);
    { dim3 g(4, 6);  k_gemm<<<g, 256>>>(tot, outw, outb, ns, 384, 250, 1012); }
    k_state<<<384, 256>>>(ns, xr, out + 384 * 4096);          // state_out -> d_out tail

    // ---- decoder ----
    { dim3 g(8, 6);  k_gemm<<<g, 256>>>(xr, dfc1w, dfc1b, d1, 384, 512, 250); }
    k_ln_act<<<384, 256>>>(d1, 512, 1);                       // ReLU
    { dim3 g(64, 6); k_gemm<<<g, 256>>>(d1, dfc2w, dfc2b, d2, 384, 4096, 512); }
    k_ln_act<<<384, 256>>>(d2, 4096, 1);                      // ReLU
    k_deconv<8,64,32,0><<<384, 256, (4096+32768+32)*4>>>(d2, d1w, d1b, dd1);
    k_deconv<16,32,16,0><<<384, 256, (8192+8192+16)*4>>>(dd1, d2w, d2b, dd2);
    k_deconv<32,16,1,1><<<384, 256, (16384+256+1)*4>>>(dd2, d3w, d3b, out); // x_out -> d_out head
}

// round 2
// speedup vs baseline: 1.6656x; 1.6656x over previous
#include <cuda_runtime.h>
#include <math.h>

#define EPSF 1e-5f

// ---------------- scratch arena ----------------
__device__ float g_scratch[26718408];

// ---------------- block reduction (blockDim.x == 256) ----------------
__device__ __forceinline__ void reduce2(float& s, float& s2) {
    __shared__ float rA[256];
    __shared__ float rB[256];
    __syncthreads();
    int t = threadIdx.x;
    rA[t] = s; rB[t] = s2;
    __syncthreads();
    for (int off = 128; off > 0; off >>= 1) {
        if (t < off) { rA[t] += rA[t + off]; rB[t] += rB[t + off]; }
        __syncthreads();
    }
    s = rA[0]; s2 = rB[0];
}

// ---------------- encoder conv (stride2, pad1, k4) + ln_all + ELU ----------------
template<int S_IN, int C_IN, int C_OUT>
__global__ void k_conv_ln_elu(const float* __restrict__ in, const float* __restrict__ w,
                              const float* __restrict__ bias, float* __restrict__ out) {
    constexpr int S_OUT = S_IN / 2;
    constexpr int NIN   = S_IN * S_IN * C_IN;
    constexpr int NW    = C_OUT * C_IN * 16;
    constexpr int NOUT  = S_OUT * S_OUT * C_OUT;
    constexpr int VEC   = (C_OUT % 4 == 0) ? 4 : 1;
    constexpr int OG    = C_OUT / VEC;
    extern __shared__ float sm[];
    float* xs = sm;                 // NIN
    float* ws = sm + NIN;           // [(i*16 + kh*4 + kw)*C_OUT + o]
    float* bs = ws + NW;
    int n = blockIdx.x, t = threadIdx.x;
    const float* inp = in + (size_t)n * NIN;
    for (int idx = t; idx < NIN; idx += 256) xs[idx] = inp[idx];
    for (int idx = t; idx < NW; idx += 256) {
        int o = idx / (C_IN * 16); int rem = idx % (C_IN * 16);
        ws[rem * C_OUT + o] = w[idx];
    }
    for (int idx = t; idx < C_OUT; idx += 256) bs[idx] = bias[idx];
    __syncthreads();

    float s = 0.f, s2 = 0.f;
    float* op = out + (size_t)n * NOUT;
    for (int it = t; it < NOUT / VEC; it += 256) {
        int og = it % OG; int ab = it / OG;
        int b = ab % S_OUT, a = ab / S_OUT;
        int o = og * VEC;
        float acc[VEC];
        #pragma unroll
        for (int v = 0; v < VEC; v++) acc[v] = bs[o + v];
        #pragma unroll
        for (int kw = 0; kw < 4; kw++) {
            int u = 2 * a - 1 + kw; if (u < 0 || u >= S_IN) continue;
            #pragma unroll
            for (int kh = 0; kh < 4; kh++) {
                int vv = 2 * b - 1 + kh; if (vv < 0 || vv >= S_IN) continue;
                const float* xb = &xs[(u * S_IN + vv) * C_IN];
                const float* wb = &ws[(kh * 4 + kw) * C_OUT + o];
                if constexpr (VEC == 4 && (C_IN % 4 == 0)) {
                    for (int i = 0; i < C_IN; i += 4) {
                        float4 xv = *reinterpret_cast<const float4*>(xb + i);
                        float4 w0 = *reinterpret_cast<const float4*>(wb + (i+0)*16*C_OUT);
                        float4 w1 = *reinterpret_cast<const float4*>(wb + (i+1)*16*C_OUT);
                        float4 w2v= *reinterpret_cast<const float4*>(wb + (i+2)*16*C_OUT);
                        float4 w3 = *reinterpret_cast<const float4*>(wb + (i+3)*16*C_OUT);
                        acc[0] += xv.x*w0.x + xv.y*w1.x + xv.z*w2v.x + xv.w*w3.x;
                        acc[1] += xv.x*w0.y + xv.y*w1.y + xv.z*w2v.y + xv.w*w3.y;
                        acc[2] += xv.x*w0.z + xv.y*w1.z + xv.z*w2v.z + xv.w*w3.z;
                        acc[3] += xv.x*w0.w + xv.y*w1.w + xv.z*w2v.w + xv.w*w3.w;
                    }
                } else if constexpr (VEC == 4) {
                    for (int i = 0; i < C_IN; i++) {
                        float xv = xb[i];
                        float4 wv = *reinterpret_cast<const float4*>(wb + i * 16 * C_OUT);
                        acc[0] += xv * wv.x; acc[1] += xv * wv.y;
                        acc[2] += xv * wv.z; acc[3] += xv * wv.w;
                    }
                } else {
                    for (int i = 0; i < C_IN; i++) acc[0] += xb[i] * wb[i * 16 * C_OUT];
                }
            }
        }
        int base = ab * C_OUT + o;
        #pragma unroll
        for (int v = 0; v < VEC; v++) { float z = acc[v]; op[base + v] = z; s += z; s2 += z * z; }
    }
    reduce2(s, s2);
    float mean = s / NOUT;
    float var  = s2 / NOUT - mean * mean;
    float rsg  = rsqrtf(var + EPSF);
    for (int idx = t; idx < NOUT; idx += 256) {
        float v = (op[idx] - mean) * rsg;
        op[idx] = v > 0.f ? v : expm1f(v);
    }
}

// ---------------- decoder: up4 + conv(stride2,pad1,k4), 4x FLOP-reduced ----------------
template<int S_IN, int C_IN, int C_OUT, int ACT>
__global__ void k_deconv(const float* __restrict__ in, const float* __restrict__ w,
                         const float* __restrict__ bias, float* __restrict__ out) {
    constexpr int S_OUT = 2 * S_IN;
    constexpr int NIN   = S_IN * S_IN * C_IN;
    constexpr int NW2   = 16 * C_IN * C_OUT;
    constexpr int NOUT  = S_OUT * S_OUT * C_OUT;
    constexpr int VEC   = (C_OUT % 4 == 0) ? 4 : 1;
    constexpr int OG    = C_OUT / VEC;
    extern __shared__ float sm[];
    float* xs = sm;
    float* w2 = sm + NIN;      // [(g*C_IN + i)*C_OUT + o]
    float* bs = w2 + NW2;
    int n = blockIdx.x, t = threadIdx.x;
    const float* inp = in + (size_t)n * NIN;
    for (int idx = t; idx < NIN; idx += 256) xs[idx] = inp[idx];
    for (int idx = t; idx < NW2; idx += 256) {
        int o = idx % C_OUT; int rem = idx / C_OUT;
        int i = rem % C_IN;  int g = rem / C_IN;
        int gb = g & 1, ga = (g >> 1) & 1, pb = (g >> 2) & 1, pa = (g >> 3) & 1;
        int kw0, kw1, kh0, kh1;
        if (pa == 0) { if (ga == 0) { kw0 = 0; kw1 = 1; } else { kw0 = 1; kw1 = 4; } }
        else         { if (ga == 0) { kw0 = 0; kw1 = 3; } else { kw0 = 3; kw1 = 4; } }
        if (pb == 0) { if (gb == 0) { kh0 = 0; kh1 = 1; } else { kh0 = 1; kh1 = 4; } }
        else         { if (gb == 0) { kh0 = 0; kh1 = 3; } else { kh0 = 3; kh1 = 4; } }
        float sum = 0.f;
        for (int kw = kw0; kw < kw1; kw++)
            for (int kh = kh0; kh < kh1; kh++)
                sum += w[((o * C_IN + i) * 4 + kh) * 4 + kw];
        w2[(g * C_IN + i) * C_OUT + o] = sum;
    }
    for (int idx = t; idx < C_OUT; idx += 256) bs[idx] = bias[idx];
    __syncthreads();

    float s = 0.f, s2 = 0.f;
    float* op = out + (size_t)n * NOUT;
    for (int it = t; it < NOUT / VEC; it += 256) {
        int og = it % OG; int ab = it / OG;
        int b = ab % S_OUT, a = ab / S_OUT;
        int o = og * VEC;
        int pa = a & 1, ma = a >> 1, pb = b & 1, mb = b >> 1;
        int sua0 = pa ? ma     : ma - 1;
        int sua1 = pa ? ma + 1 : ma;
        int svb0 = pb ? mb     : mb - 1;
        int svb1 = pb ? mb + 1 : mb;
        float acc[VEC];
        #pragma unroll
        for (int v = 0; v < VEC; v++) acc[v] = bs[o + v];
        #pragma unroll
        for (int ga = 0; ga < 2; ga++) {
            int su = ga ? sua1 : sua0; if (su < 0 || su >= S_IN) continue;
            #pragma unroll
            for (int gb = 0; gb < 2; gb++) {
                int sv = gb ? svb1 : svb0; if (sv < 0 || sv >= S_IN) continue;
                const float* xb = &xs[(su * S_IN + sv) * C_IN];
                const float* wb = &w2[((((pa * 2 + pb) * 2 + ga) * 2 + gb) * C_IN) * C_OUT + o];
                if constexpr (VEC == 4 && (C_IN % 4 == 0)) {
                    for (int i = 0; i < C_IN; i += 4) {
                        float4 xv = *reinterpret_cast<const float4*>(xb + i);
                        float4 w0 = *reinterpret_cast<const float4*>(wb + (i+0)*C_OUT);
                        float4 w1 = *reinterpret_cast<const float4*>(wb + (i+1)*C_OUT);
                        float4 w2v= *reinterpret_cast<const float4*>(wb + (i+2)*C_OUT);
                        float4 w3 = *reinterpret_cast<const float4*>(wb + (i+3)*C_OUT);
                        acc[0] += xv.x*w0.x + xv.y*w1.x + xv.z*w2v.x + xv.w*w3.x;
                        acc[1] += xv.x*w0.y + xv.y*w1.y + xv.z*w2v.y + xv.w*w3.y;
                        acc[2] += xv.x*w0.z + xv.y*w1.z + xv.z*w2v.z + xv.w*w3.z;
                        acc[3] += xv.x*w0.w + xv.y*w1.w + xv.z*w2v.w + xv.w*w3.w;
                    }
                } else if constexpr (VEC == 1 && (C_IN % 4 == 0)) {
                    // C_OUT==1: w stride in i is 1 -> vectorize both
                    for (int i = 0; i < C_IN; i += 4) {
                        float4 xv = *reinterpret_cast<const float4*>(xb + i);
                        float4 wv = *reinterpret_cast<const float4*>(wb + i);
                        acc[0] += xv.x*wv.x + xv.y*wv.y + xv.z*wv.z + xv.w*wv.w;
                    }
                } else {
                    for (int i = 0; i < C_IN; i++) acc[0] += xb[i] * wb[i * C_OUT];
                }
            }
        }
        int base = ab * C_OUT + o;
        if (ACT == 1) {
            #pragma unroll
            for (int v = 0; v < VEC; v++) op[base + v] = 1.f / (1.f + expf(-acc[v]));
        } else {
            #pragma unroll
            for (int v = 0; v < VEC; v++) { float z = acc[v]; op[base + v] = z; s += z; s2 += z * z; }
        }
    }
    if (ACT == 0) {
        reduce2(s, s2);
        float mean = s / NOUT;
        float var  = s2 / NOUT - mean * mean;
        float rsg  = rsqrtf(var + EPSF);
        for (int idx = t; idx < NOUT; idx += 256) {
            float v = (op[idx] - mean) * rsg;
            op[idx] = v > 0.f ? v : 0.f;
        }
    }
}

// ---------------- split-K tiled GEMM ----------------
// grid = (ceil(N/64), ceil(M/64), nsplit). Each z handles ksteps_split chunks of 16.
// If gridDim.z==1 writes C+bias; else writes partial at C + z*M*N (bias must be null).
__global__ void k_gemm2(const float* __restrict__ A, const float* __restrict__ B,
                        const float* __restrict__ bias, float* __restrict__ C,
                        int M, int N, int K, int ksteps_split) {
    __shared__ float As[16][68];
    __shared__ float Bs[16][68];
    int tx = threadIdx.x % 16, ty = threadIdx.x / 16;
    int n0 = blockIdx.x * 64, m0 = blockIdx.y * 64;
    int k_begin = blockIdx.z * ksteps_split * 16;
    int k_end = min(K, k_begin + ksteps_split * 16);
    float acc[4][4] = {};
    for (int k0 = k_begin; k0 < k_end; k0 += 16) {
        #pragma unroll
        for (int r = 0; r < 4; r++) {
            int idx = threadIdx.x + r * 256;
            int mm = idx >> 4, kk = idx & 15;
            int gm = m0 + mm, gk = k0 + kk;
            As[kk][mm] = (gm < M && gk < K) ? A[(size_t)gm * K + gk] : 0.f;
            int kk2 = idx >> 6, nn = idx & 63;
            int gk2 = k0 + kk2, gn = n0 + nn;
            Bs[kk2][nn] = (gk2 < K && gn < N) ? B[(size_t)gk2 * N + gn] : 0.f;
        }
        __syncthreads();
        #pragma unroll
        for (int k = 0; k < 16; k++) {
            float4 a4 = *reinterpret_cast<const float4*>(&As[k][ty * 4]);
            float4 b4 = *reinterpret_cast<const float4*>(&Bs[k][tx * 4]);
            float av[4] = {a4.x, a4.y, a4.z, a4.w};
            float bv[4] = {b4.x, b4.y, b4.z, b4.w};
            #pragma unroll
            for (int i = 0; i < 4; i++)
                #pragma unroll
                for (int j = 0; j < 4; j++) acc[i][j] += av[i] * bv[j];
        }
        __syncthreads();
    }
    float* Cw = C + (size_t)blockIdx.z * M * N;
    #pragma unroll
    for (int i = 0; i < 4; i++) {
        int m = m0 + ty * 4 + i; if (m >= M) continue;
        #pragma unroll
        for (int j = 0; j < 4; j++) {
            int nn = n0 + tx * 4 + j; if (nn >= N) continue;
            Cw[(size_t)m * N + nn] = acc[i][j] + (bias ? bias[nn] : 0.f);
        }
    }
}

// ---------------- split-K reduce + optional bias + optional row-LN + act ----------------
// act: -1 = plain sum(+bias), 0 = LN+ELU, 1 = LN+ReLU.  grid = M rows, N <= 512 for LN.
__global__ void k_reduce_ln(const float* __restrict__ part, const float* __restrict__ bias,
                            float* __restrict__ out, int M, int N, int nsplit, int act) {
    __shared__ float row[512];
    int r = blockIdx.x;
    float s = 0.f, s2 = 0.f;
    for (int c = threadIdx.x; c < N; c += 256) {
        float v = bias ? bias[c] : 0.f;
        for (int z = 0; z < nsplit; z++) v += part[((size_t)z * M + r) * N + c];
        if (act < 0) { out[(size_t)r * N + c] = v; }
        else { row[c] = v; s += v; s2 += v * v; }
    }
    if (act < 0) return;
    reduce2(s, s2);
    float mean = s / N, var = s2 / N - mean * mean, rsg = rsqrtf(var + EPSF);
    for (int c = threadIdx.x; c < N; c += 256) {
        float v = (row[c] - mean) * rsg;
        out[(size_t)r * N + c] = (act == 0) ? (v > 0.f ? v : expm1f(v)) : (v > 0.f ? v : 0.f);
    }
}

// ---------------- per-row layernorm + activation, in-place (for wide rows) ----------------
__global__ void k_ln_act(float* __restrict__ X, int N, int act) {
    int r = blockIdx.x;
    float* x = X + (size_t)r * N;
    float s = 0.f, s2 = 0.f;
    for (int c = threadIdx.x; c < N; c += 256) { float v = x[c]; s += v; s2 += v * v; }
    reduce2(s, s2);
    float mean = s / N, var = s2 / N - mean * mean, rsg = rsqrtf(var + EPSF);
    for (int c = threadIdx.x; c < N; c += 256) {
        float v = (x[c] - mean) * rsg;
        x[c] = (act == 0) ? (v > 0.f ? v : expm1f(v)) : (v > 0.f ? v : 0.f);
    }
}

// ---------------- build Bcat[250][500] = [corew_rows0..249 | corew_rows250..499] ----------------
__global__ void k_catW(const float* __restrict__ corew, float* __restrict__ Bcat) {
    int idx = blockIdx.x * 256 + threadIdx.x;
    if (idx >= 250 * 500) return;
    int k = idx / 500, n = idx % 500;
    Bcat[idx] = (n < 250) ? corew[k * 250 + n] : corew[(k + 250) * 250 + (n - 250)];
}

// ---------------- core rows: relu(ln( AB[fi][0:250] + AB[bi*8+j][250:500] + bias )) ----------------
__global__ void k_core(const float* __restrict__ AB, const float* __restrict__ bias,
                       float* __restrict__ core) {
    int r = blockIdx.x;                  // r = (bi*8+i)*7 + jj
    int jj = r % 7; int fi = r / 7; int i = fi % 8; int bi = fi / 8;
    int j = (jj < i) ? jj : jj + 1;
    const float* ar = AB + (size_t)fi * 500;
    const float* br = AB + (size_t)(bi * 8 + j) * 500 + 250;
    __shared__ float row[256];
    float s = 0.f, s2 = 0.f;
    for (int c = threadIdx.x; c < 250; c += 256) {
        float v = ar[c] + br[c] + bias[c];
        row[c] = v; s += v; s2 += v * v;
    }
    reduce2(s, s2);
    float mean = s / 250.f, var = s2 / 250.f - mean * mean, rsg = rsqrtf(var + EPSF);
    float* o = core + (size_t)r * 250;
    for (int c = threadIdx.x; c < 250; c += 256) {
        float v = (row[c] - mean) * rsg;
        o[c] = v > 0.f ? v : 0.f;
    }
}

// ---------------- att: sigmoid( tanh(ln(att1_row)) . att2_w + att2_b ) ----------------
__global__ void k_att(const float* __restrict__ X, const float* __restrict__ w2,
                      const float* __restrict__ b2, float* __restrict__ att) {
    int r = blockIdx.x;
    const float* x = X + (size_t)r * 100;
    float s = 0.f, s2 = 0.f;
    for (int c = threadIdx.x; c < 100; c += 256) { float v = x[c]; s += v; s2 += v * v; }
    reduce2(s, s2);
    float mean = s / 100.f, var = s2 / 100.f - mean * mean, rsg = rsqrtf(var + EPSF);
    float d = 0.f;
    for (int c = threadIdx.x; c < 100; c += 256) {
        float v = tanhf((x[c] - mean) * rsg);
        d += v * w2[c];
    }
    float dummy = 0.f;
    reduce2(d, dummy);
    if (threadIdx.x == 0) att[r] = 1.f / (1.f + expf(-(d + b2[0])));
}

// ---------------- effect[fi, c] = sum_jj ctx[fi*7+jj, c] * att[fi*7+jj] ----------------
__global__ void k_eff(const float* __restrict__ ctx, const float* __restrict__ att,
                      float* __restrict__ eff) {
    int idx = blockIdx.x * 256 + threadIdx.x;
    if (idx >= 384 * 250) return;
    int c = idx % 250; int fi = idx / 250;
    float s = 0.f;
    #pragma unroll
    for (int jj = 0; jj < 7; jj++)
        s += ctx[((size_t)fi * 7 + jj) * 250 + c] * att[fi * 7 + jj];
    eff[idx] = s;
}

// ---------------- total = concat([s1, effect, h], axis=1) ----------------
__global__ void k_total(const float* __restrict__ s1, const float* __restrict__ eff,
                        const float* __restrict__ h, float* __restrict__ total) {
    int idx = blockIdx.x * 256 + threadIdx.x;
    if (idx >= 384 * 1012) return;
    int n = idx / 1012, c = idx % 1012;
    float v = (c < 250) ? s1[n * 250 + c]
            : (c < 500) ? eff[n * 250 + (c - 250)]
                        : h[n * 512 + (c - 500)];
    total[idx] = v;
}

// ---------------- xr = sigmoid(ln(ns)); state_out = sigmoid(ns) ----------------
__global__ void k_state(const float* __restrict__ ns, float* __restrict__ xr,
                        float* __restrict__ so) {
    int r = blockIdx.x;
    const float* x = ns + (size_t)r * 250;
    float s = 0.f, s2 = 0.f;
    for (int c = threadIdx.x; c < 250; c += 256) { float v = x[c]; s += v; s2 += v * v; }
    reduce2(s, s2);
    float mean = s / 250.f, var = s2 / 250.f - mean * mean, rsg = rsqrtf(var + EPSF);
    for (int c = threadIdx.x; c < 250; c += 256) {
        float v = x[c];
        xr[(size_t)r * 250 + c] = 1.f / (1.f + expf(-((v - mean) * rsg)));
        so[(size_t)r * 250 + c] = 1.f / (1.f + expf(-v));
    }
}

// ---------------- launch ----------------
extern "C" void kernel_launch(void* const* d_in, const int* in_sizes, int n_in,
                              void* d_out, int out_size) {
    const float* x     = (const float*)d_in[0];
    const float* state = (const float*)d_in[1];
    const float* c1w   = (const float*)d_in[2];  const float* c1b  = (const float*)d_in[3];
    const float* c2w   = (const float*)d_in[4];  const float* c2b  = (const float*)d_in[5];
    const float* c3w   = (const float*)d_in[6];  const float* c3b  = (const float*)d_in[7];
    const float* efcw  = (const float*)d_in[8];  const float* efcb = (const float*)d_in[9];
    const float* rencw = (const float*)d_in[10]; const float* rencb= (const float*)d_in[11];
    const float* corew = (const float*)d_in[12]; const float* coreb= (const float*)d_in[13];
    const float* ctxw  = (const float*)d_in[14]; const float* ctxb = (const float*)d_in[15];
    const float* att1w = (const float*)d_in[16]; const float* att1b= (const float*)d_in[17];
    const float* att2w = (const float*)d_in[18]; const float* att2b= (const float*)d_in[19];
    const float* outw  = (const float*)d_in[20]; const float* outb = (const float*)d_in[21];
    const float* dfc1w = (const float*)d_in[22]; const float* dfc1b= (const float*)d_in[23];
    const float* dfc2w = (const float*)d_in[24]; const float* dfc2b= (const float*)d_in[25];
    const float* d1w   = (const float*)d_in[26]; const float* d1b  = (const float*)d_in[27];
    const float* d2w   = (const float*)d_in[28]; const float* d2b  = (const float*)d_in[29];
    const float* d3w   = (const float*)d_in[30]; const float* d3b  = (const float*)d_in[31];
    float* out = (float*)d_out;

    float* S = nullptr;
    cudaGetSymbolAddress((void**)&S, g_scratch);
    float* h1   = S;                    // 6291456
    float* h2   = h1  + 6291456;        // 3145728
    float* h3   = h2  + 3145728;        // 1572864
    float* hf   = h3  + 1572864;        // 196608
    float* s1   = hf  + 196608;         // 96000
    float* AB   = s1  + 96000;          // 192000 (384x500)
    float* core = AB  + 192000;         // 672000
    float* ctx  = core+ 672000;         // 672000
    float* att1 = ctx + 672000;         // 268800
    float* att  = att1+ 268800;         // 2688
    float* eff  = att + 2688;           // 96000
    float* tot  = eff + 96000;          // 388608
    float* ns   = tot + 388608;         // 96000
    float* xr   = ns  + 96000;          // 96000
    float* d1   = xr  + 96000;          // 196608
    float* d2   = d1  + 196608;         // 1572864
    float* dd1  = d2  + 1572864;        // 3145728
    float* dd2  = dd1 + 3145728;        // 6291456
    float* Bcat = dd2 + 6291456;        // 125000
    float* part = Bcat+ 125000;         // 1600000

    cudaFuncSetAttribute(k_conv_ln_elu<32,16,32>, cudaFuncAttributeMaxDynamicSharedMemorySize, (16384+8192+32)*4);
    cudaFuncSetAttribute(k_conv_ln_elu<16,32,64>, cudaFuncAttributeMaxDynamicSharedMemorySize, (8192+32768+64)*4);
    cudaFuncSetAttribute(k_deconv<8,64,32,0>,     cudaFuncAttributeMaxDynamicSharedMemorySize, (4096+32768+32)*4);
    cudaFuncSetAttribute(k_deconv<16,32,16,0>,    cudaFuncAttributeMaxDynamicSharedMemorySize, (8192+8192+16)*4);
    cudaFuncSetAttribute(k_deconv<32,16,1,1>,     cudaFuncAttributeMaxDynamicSharedMemorySize, (16384+256+1)*4);

    const float* NOB = nullptr;

    // ---- encoder ----
    k_conv_ln_elu<64,1,16><<<384, 256, (4096+256+16)*4>>>(x, c1w, c1b, h1);
    k_conv_ln_elu<32,16,32><<<384, 256, (16384+8192+32)*4>>>(h1, c2w, c2b, h2);
    k_conv_ln_elu<16,32,64><<<384, 256, (8192+32768+64)*4>>>(h2, c3w, c3b, h3);
    // efc: M384 N512 K4096, split 8 (32 ksteps each) -> LN+ELU fused in reduce
    { dim3 g(8, 6, 8); k_gemm2<<<g, 256>>>(h3, efcw, NOB, part, 384, 512, 4096, 32); }
    k_reduce_ln<<<384, 256>>>(part, efcb, hf, 384, 512, 8, 0);

    // ---- recurrent / pairwise ----
    // renc: M384 N250 K250, split 4 (4 ksteps) -> LN+ReLU
    { dim3 g(4, 6, 4); k_gemm2<<<g, 256>>>(state, rencw, NOB, part, 384, 250, 250, 4); }
    k_reduce_ln<<<384, 256>>>(part, rencb, s1, 384, 250, 4, 1);
    // AB = s1 @ [W1|W2]: M384 N500 K250, split 4 -> plain
    k_catW<<<(125000 + 255) / 256, 256>>>(corew, Bcat);
    { dim3 g(8, 6, 4); k_gemm2<<<g, 256>>>(s1, Bcat, NOB, part, 384, 500, 250, 4); }
    k_reduce_ln<<<384, 256>>>(part, NOB, AB, 384, 500, 4, -1);
    k_core<<<2688, 256>>>(AB, coreb, core);
    // ctx: M2688 N250 K250, split 2 (8 ksteps) -> LN+ReLU
    { dim3 g(4, 42, 2); k_gemm2<<<g, 256>>>(core, ctxw, NOB, part, 2688, 250, 250, 8); }
    k_reduce_ln<<<2688, 256>>>(part, ctxb, ctx, 2688, 250, 2, 1);
    // att1: M2688 N100 K250, split 4 -> plain (+bias)
    { dim3 g(2, 42, 4); k_gemm2<<<g, 256>>>(core, att1w, NOB, part, 2688, 100, 250, 4); }
    k_reduce_ln<<<2688, 256>>>(part, att1b, att1, 2688, 100, 4, -1);
    k_att<<<2688, 256>>>(att1, att2w, att2b, att);
    k_eff<<<(96000 + 255) / 256, 256>>>(ctx, att, eff);
    k_total<<<(388608 + 255) / 256, 256>>>(s1, eff, hf, tot);
    // out: M384 N250 K1012 (64 ksteps), split 8 (8 each) -> plain (+bias)
    { dim3 g(4, 6, 8); k_gemm2<<<g, 256>>>(tot, outw, NOB, part, 384, 250, 1012, 8); }
    k_reduce_ln<<<384, 256>>>(part, outb, ns, 384, 250, 8, -1);
    k_state<<<384, 256>>>(ns, xr, out + 384 * 4096);

    // ---- decoder ----
    // dfc1: M384 N512 K250, split 4 -> LN+ReLU
    { dim3 g(8, 6, 4); k_gemm2<<<g, 256>>>(xr, dfc1w, NOB, part, 384, 512, 250, 4); }
    k_reduce_ln<<<384, 256>>>(part, dfc1b, d1, 384, 512, 4, 1);
    // dfc2: M384 N4096 K512 (32 ksteps), no split (384 tiles) -> direct + bias, then LN
    { dim3 g(64, 6, 1); k_gemm2<<<g, 256>>>(d1, dfc2w, dfc2b, d2, 384, 4096, 512, 32); }
    k_ln_act<<<384, 256>>>(d2, 4096, 1);
    k_deconv<8,64,32,0><<<384, 256, (4096+32768+32)*4>>>(d2, d1w, d1b, dd1);
    k_deconv<16,32,16,0><<<384, 256, (8192+8192+16)*4>>>(dd1, d2w, d2b, dd2);
    k_deconv<32,16,1,1><<<384, 256, (16384+256+1)*4>>>(dd2, d3w, d3b, out);
}

// round 3
// speedup vs baseline: 2.1613x; 1.2977x over previous
#include <cuda_runtime.h>
#include <math.h>

#define EPSF 1e-5f

// ---------------- scratch arena ----------------
__device__ float g_scratch[26718408];

// ---------------- block reduction (blockDim.x == 256) ----------------
__device__ __forceinline__ void reduce2(float& s, float& s2) {
    __shared__ float rA[256];
    __shared__ float rB[256];
    __syncthreads();
    int t = threadIdx.x;
    rA[t] = s; rB[t] = s2;
    __syncthreads();
    for (int off = 128; off > 0; off >>= 1) {
        if (t < off) { rA[t] += rA[t + off]; rB[t] += rB[t + off]; }
        __syncthreads();
    }
    s = rA[0]; s2 = rB[0];
}

// ---------------- pixel-blocked encoder conv (stride2,pad1,k4) + ln_all + ELU ----------------
// Each thread: P consecutive-b output pixels x 4 output channels. Weights in smem,
// layout [(tap*C_IN + i)*C_OUT + o] so a float4 weight quad is reused across P pixels.
template<int S_IN, int C_IN, int C_OUT, int P>
__global__ void k_conv_b(const float* __restrict__ in, const float* __restrict__ w,
                         const float* __restrict__ bias, float* __restrict__ out) {
    constexpr int S_OUT = S_IN / 2;
    constexpr int NIN   = S_IN * S_IN * C_IN;
    constexpr int NW    = C_OUT * C_IN * 16;
    constexpr int NOUT  = S_OUT * S_OUT * C_OUT;
    constexpr int OG    = C_OUT / 4;
    constexpr int BG    = S_OUT / P;
    constexpr int UNITS = OG * S_OUT * BG;
    extern __shared__ float sm[];
    float* xs = sm;
    float* ws = sm + NIN;
    float* bs = ws + NW;
    int n = blockIdx.x, t = threadIdx.x;
    const float* inp = in + (size_t)n * NIN;
    for (int idx = t; idx < NIN; idx += 256) xs[idx] = inp[idx];
    for (int idx = t; idx < NW; idx += 256) {
        int o = idx / (C_IN * 16); int rem = idx % (C_IN * 16);
        int i = rem / 16; int tap = rem % 16;          // tap = kh*4+kw
        ws[(tap * C_IN + i) * C_OUT + o] = w[idx];
    }
    for (int idx = t; idx < C_OUT; idx += 256) bs[idx] = bias[idx];
    __syncthreads();

    float s = 0.f, s2 = 0.f;
    float* op = out + (size_t)n * NOUT;
    for (int u = t; u < UNITS; u += 256) {
        int og = u % OG; int rest = u / OG;
        int bg = rest % BG; int a = rest / BG;
        int o = og * 4;
        float acc[P][4];
        #pragma unroll
        for (int p = 0; p < P; p++)
            #pragma unroll
            for (int v = 0; v < 4; v++) acc[p][v] = bs[o + v];
        #pragma unroll
        for (int kw = 0; kw < 4; kw++) {
            int ua = 2 * a - 1 + kw;
            if (ua < 0 || ua >= S_IN) continue;
            #pragma unroll
            for (int kh = 0; kh < 4; kh++) {
                bool vld[P]; int vb[P];
                #pragma unroll
                for (int p = 0; p < P; p++) {
                    int b = bg * P + p;
                    int v = 2 * b - 1 + kh;
                    vld[p] = (v >= 0 && v < S_IN); vb[p] = v;
                }
                const float* wt = &ws[((kh * 4 + kw) * C_IN) * C_OUT + o];
                if constexpr (C_IN == 1) {
                    float4 wv = *reinterpret_cast<const float4*>(wt);
                    #pragma unroll
                    for (int p = 0; p < P; p++) {
                        if (vld[p]) {
                            float xv = xs[ua * S_IN + vb[p]];
                            acc[p][0] += xv * wv.x; acc[p][1] += xv * wv.y;
                            acc[p][2] += xv * wv.z; acc[p][3] += xv * wv.w;
                        }
                    }
                } else {
                    #pragma unroll 4
                    for (int i = 0; i < C_IN; i += 4) {
                        float4 w0 = *reinterpret_cast<const float4*>(wt + (i+0) * C_OUT);
                        float4 w1 = *reinterpret_cast<const float4*>(wt + (i+1) * C_OUT);
                        float4 w2v= *reinterpret_cast<const float4*>(wt + (i+2) * C_OUT);
                        float4 w3 = *reinterpret_cast<const float4*>(wt + (i+3) * C_OUT);
                        #pragma unroll
                        for (int p = 0; p < P; p++) {
                            if (vld[p]) {
                                float4 xv = *reinterpret_cast<const float4*>(
                                    &xs[(ua * S_IN + vb[p]) * C_IN + i]);
                                acc[p][0] += xv.x*w0.x + xv.y*w1.x + xv.z*w2v.x + xv.w*w3.x;
                                acc[p][1] += xv.x*w0.y + xv.y*w1.y + xv.z*w2v.y + xv.w*w3.y;
                                acc[p][2] += xv.x*w0.z + xv.y*w1.z + xv.z*w2v.z + xv.w*w3.z;
                                acc[p][3] += xv.x*w0.w + xv.y*w1.w + xv.z*w2v.w + xv.w*w3.w;
                            }
                        }
                    }
                }
            }
        }
        #pragma unroll
        for (int p = 0; p < P; p++) {
            int base = (a * S_OUT + bg * P + p) * C_OUT + o;
            #pragma unroll
            for (int v = 0; v < 4; v++) {
                float z = acc[p][v];
                op[base + v] = z; s += z; s2 += z * z;
            }
        }
    }
    reduce2(s, s2);
    float mean = s / NOUT;
    float var  = s2 / NOUT - mean * mean;
    float rsg  = rsqrtf(var + EPSF);
    for (int idx = t; idx < NOUT; idx += 256) {
        float v = (op[idx] - mean) * rsg;
        op[idx] = v > 0.f ? v : expm1f(v);
    }
}

// ---------------- pixel-blocked decoder: up4 + conv(stride2,pad1,k4), 4x FLOP-reduced ----------------
// Pixel group: P pixels with the SAME parity pb (b = 2*mb + pb), so aggregated
// weights (parity-indexed) are shared across the group.
// ACT==0: ln_all + ReLU.  ACT==1: sigmoid (final layer).
template<int S_IN, int C_IN, int C_OUT, int P, int ACT>
__global__ void k_deconv_b(const float* __restrict__ in, const float* __restrict__ w,
                           const float* __restrict__ bias, float* __restrict__ out) {
    constexpr int S_OUT = 2 * S_IN;
    constexpr int NIN   = S_IN * S_IN * C_IN;
    constexpr int NW2   = 16 * C_IN * C_OUT;
    constexpr int NOUT  = S_OUT * S_OUT * C_OUT;
    constexpr int VEC   = (C_OUT % 4 == 0) ? 4 : 1;
    constexpr int OG    = C_OUT / VEC;
    constexpr int MBG   = S_IN / P;
    constexpr int UNITS = OG * S_OUT * 2 * MBG;
    extern __shared__ float sm[];
    float* xs = sm;
    float* w2 = sm + NIN;      // [(g*C_IN + i)*C_OUT + o]
    float* bs = w2 + NW2;
    int n = blockIdx.x, t = threadIdx.x;
    const float* inp = in + (size_t)n * NIN;
    for (int idx = t; idx < NIN; idx += 256) xs[idx] = inp[idx];
    for (int idx = t; idx < NW2; idx += 256) {
        int o = idx % C_OUT; int rem = idx / C_OUT;
        int i = rem % C_IN;  int g = rem / C_IN;
        int gb = g & 1, ga = (g >> 1) & 1, pb = (g >> 2) & 1, pa = (g >> 3) & 1;
        int kw0, kw1, kh0, kh1;
        if (pa == 0) { if (ga == 0) { kw0 = 0; kw1 = 1; } else { kw0 = 1; kw1 = 4; } }
        else         { if (ga == 0) { kw0 = 0; kw1 = 3; } else { kw0 = 3; kw1 = 4; } }
        if (pb == 0) { if (gb == 0) { kh0 = 0; kh1 = 1; } else { kh0 = 1; kh1 = 4; } }
        else         { if (gb == 0) { kh0 = 0; kh1 = 3; } else { kh0 = 3; kh1 = 4; } }
        float sum = 0.f;
        for (int kw = kw0; kw < kw1; kw++)
            for (int kh = kh0; kh < kh1; kh++)
                sum += w[((o * C_IN + i) * 4 + kh) * 4 + kw];
        w2[(g * C_IN + i) * C_OUT + o] = sum;
    }
    for (int idx = t; idx < C_OUT; idx += 256) bs[idx] = bias[idx];
    __syncthreads();

    float s = 0.f, s2 = 0.f;
    float* op = out + (size_t)n * NOUT;
    for (int u = t; u < UNITS; u += 256) {
        int og = u % OG; int rest = u / OG;
        int mbg = rest % MBG; rest /= MBG;
        int pb = rest & 1; int a = rest >> 1;
        int o = og * VEC;
        int pa = a & 1, ma = a >> 1;
        int su0 = pa ? ma : ma - 1;
        int su1 = pa ? ma + 1 : ma;
        float acc[P][VEC];
        #pragma unroll
        for (int p = 0; p < P; p++)
            #pragma unroll
            for (int v = 0; v < VEC; v++) acc[p][v] = bs[o + v];
        #pragma unroll
        for (int ga = 0; ga < 2; ga++) {
            int su = ga ? su1 : su0;
            if (su < 0 || su >= S_IN) continue;
            #pragma unroll
            for (int gb = 0; gb < 2; gb++) {
                bool vld[P]; int svv[P];
                #pragma unroll
                for (int p = 0; p < P; p++) {
                    int mb = mbg * P + p;
                    int sv = gb ? (pb ? mb + 1 : mb) : (pb ? mb : mb - 1);
                    vld[p] = (sv >= 0 && sv < S_IN); svv[p] = sv;
                }
                int g = ((pa * 2 + pb) * 2 + ga) * 2 + gb;
                const float* wb = &w2[(g * C_IN) * C_OUT + o];
                if constexpr (VEC == 4) {
                    #pragma unroll 4
                    for (int i = 0; i < C_IN; i += 4) {
                        float4 w0 = *reinterpret_cast<const float4*>(wb + (i+0) * C_OUT);
                        float4 w1 = *reinterpret_cast<const float4*>(wb + (i+1) * C_OUT);
                        float4 w2v= *reinterpret_cast<const float4*>(wb + (i+2) * C_OUT);
                        float4 w3 = *reinterpret_cast<const float4*>(wb + (i+3) * C_OUT);
                        #pragma unroll
                        for (int p = 0; p < P; p++) {
                            if (vld[p]) {
                                float4 xv = *reinterpret_cast<const float4*>(
                                    &xs[(su * S_IN + svv[p]) * C_IN + i]);
                                acc[p][0] += xv.x*w0.x + xv.y*w1.x + xv.z*w2v.x + xv.w*w3.x;
                                acc[p][1] += xv.x*w0.y + xv.y*w1.y + xv.z*w2v.y + xv.w*w3.y;
                                acc[p][2] += xv.x*w0.z + xv.y*w1.z + xv.z*w2v.z + xv.w*w3.z;
                                acc[p][3] += xv.x*w0.w + xv.y*w1.w + xv.z*w2v.w + xv.w*w3.w;
                            }
                        }
                    }
                } else {
                    // C_OUT == 1: weight row contiguous in i
                    #pragma unroll 4
                    for (int i = 0; i < C_IN; i += 4) {
                        float4 wv = *reinterpret_cast<const float4*>(wb + i);
                        #pragma unroll
                        for (int p = 0; p < P; p++) {
                            if (vld[p]) {
                                float4 xv = *reinterpret_cast<const float4*>(
                                    &xs[(su * S_IN + svv[p]) * C_IN + i]);
                                acc[p][0] += xv.x*wv.x + xv.y*wv.y + xv.z*wv.z + xv.w*wv.w;
                            }
                        }
                    }
                }
            }
        }
        #pragma unroll
        for (int p = 0; p < P; p++) {
            int b = 2 * (mbg * P + p) + pb;
            int base = (a * S_OUT + b) * C_OUT + o;
            if (ACT == 1) {
                #pragma unroll
                for (int v = 0; v < VEC; v++) op[base + v] = 1.f / (1.f + expf(-acc[p][v]));
            } else {
                #pragma unroll
                for (int v = 0; v < VEC; v++) {
                    float z = acc[p][v]; op[base + v] = z; s += z; s2 += z * z;
                }
            }
        }
    }
    if (ACT == 0) {
        reduce2(s, s2);
        float mean = s / NOUT;
        float var  = s2 / NOUT - mean * mean;
        float rsg  = rsqrtf(var + EPSF);
        for (int idx = t; idx < NOUT; idx += 256) {
            float v = (op[idx] - mean) * rsg;
            op[idx] = v > 0.f ? v : 0.f;
        }
    }
}

// ---------------- split-K tiled GEMM ----------------
__global__ void k_gemm2(const float* __restrict__ A, const float* __restrict__ B,
                        const float* __restrict__ bias, float* __restrict__ C,
                        int M, int N, int K, int ksteps_split) {
    __shared__ float As[16][68];
    __shared__ float Bs[16][68];
    int tx = threadIdx.x % 16, ty = threadIdx.x / 16;
    int n0 = blockIdx.x * 64, m0 = blockIdx.y * 64;
    int k_begin = blockIdx.z * ksteps_split * 16;
    int k_end = min(K, k_begin + ksteps_split * 16);
    float acc[4][4] = {};
    for (int k0 = k_begin; k0 < k_end; k0 += 16) {
        #pragma unroll
        for (int r = 0; r < 4; r++) {
            int idx = threadIdx.x + r * 256;
            int mm = idx >> 4, kk = idx & 15;
            int gm = m0 + mm, gk = k0 + kk;
            As[kk][mm] = (gm < M && gk < K) ? A[(size_t)gm * K + gk] : 0.f;
            int kk2 = idx >> 6, nn = idx & 63;
            int gk2 = k0 + kk2, gn = n0 + nn;
            Bs[kk2][nn] = (gk2 < K && gn < N) ? B[(size_t)gk2 * N + gn] : 0.f;
        }
        __syncthreads();
        #pragma unroll
        for (int k = 0; k < 16; k++) {
            float4 a4 = *reinterpret_cast<const float4*>(&As[k][ty * 4]);
            float4 b4 = *reinterpret_cast<const float4*>(&Bs[k][tx * 4]);
            float av[4] = {a4.x, a4.y, a4.z, a4.w};
            float bv[4] = {b4.x, b4.y, b4.z, b4.w};
            #pragma unroll
            for (int i = 0; i < 4; i++)
                #pragma unroll
                for (int j = 0; j < 4; j++) acc[i][j] += av[i] * bv[j];
        }
        __syncthreads();
    }
    float* Cw = C + (size_t)blockIdx.z * M * N;
    #pragma unroll
    for (int i = 0; i < 4; i++) {
        int m = m0 + ty * 4 + i; if (m >= M) continue;
        #pragma unroll
        for (int j = 0; j < 4; j++) {
            int nn = n0 + tx * 4 + j; if (nn >= N) continue;
            Cw[(size_t)m * N + nn] = acc[i][j] + (bias ? bias[nn] : 0.f);
        }
    }
}

// ---------------- split-K reduce + bias + optional row-LN + act ----------------
__global__ void k_reduce_ln(const float* __restrict__ part, const float* __restrict__ bias,
                            float* __restrict__ out, int M, int N, int nsplit, int act) {
    __shared__ float row[512];
    int r = blockIdx.x;
    float s = 0.f, s2 = 0.f;
    for (int c = threadIdx.x; c < N; c += 256) {
        float v = bias ? bias[c] : 0.f;
        for (int z = 0; z < nsplit; z++) v += part[((size_t)z * M + r) * N + c];
        if (act < 0) { out[(size_t)r * N + c] = v; }
        else { row[c] = v; s += v; s2 += v * v; }
    }
    if (act < 0) return;
    reduce2(s, s2);
    float mean = s / N, var = s2 / N - mean * mean, rsg = rsqrtf(var + EPSF);
    for (int c = threadIdx.x; c < N; c += 256) {
        float v = (row[c] - mean) * rsg;
        out[(size_t)r * N + c] = (act == 0) ? (v > 0.f ? v : expm1f(v)) : (v > 0.f ? v : 0.f);
    }
}

// ---------------- per-row layernorm + act, in-place (wide rows) ----------------
__global__ void k_ln_act(float* __restrict__ X, int N, int act) {
    int r = blockIdx.x;
    float* x = X + (size_t)r * N;
    float s = 0.f, s2 = 0.f;
    for (int c = threadIdx.x; c < N; c += 256) { float v = x[c]; s += v; s2 += v * v; }
    reduce2(s, s2);
    float mean = s / N, var = s2 / N - mean * mean, rsg = rsqrtf(var + EPSF);
    for (int c = threadIdx.x; c < N; c += 256) {
        float v = (x[c] - mean) * rsg;
        x[c] = (act == 0) ? (v > 0.f ? v : expm1f(v)) : (v > 0.f ? v : 0.f);
    }
}

// ---------------- Bcat[250][500] = [corew_rows0..249 | corew_rows250..499] ----------------
__global__ void k_catW(const float* __restrict__ corew, float* __restrict__ Bcat) {
    int idx = blockIdx.x * 256 + threadIdx.x;
    if (idx >= 250 * 500) return;
    int k = idx / 500, n = idx % 500;
    Bcat[idx] = (n < 250) ? corew[k * 250 + n] : corew[(k + 250) * 250 + (n - 250)];
}

// ---------------- core rows: relu(ln( AB[fi][0:250] + AB[bi*8+j][250:500] + bias )) ----------------
__global__ void k_core(const float* __restrict__ AB, const float* __restrict__ bias,
                       float* __restrict__ core) {
    int r = blockIdx.x;                  // r = (bi*8+i)*7 + jj
    int jj = r % 7; int fi = r / 7; int i = fi % 8; int bi = fi / 8;
    int j = (jj < i) ? jj : jj + 1;
    const float* ar = AB + (size_t)fi * 500;
    const float* br = AB + (size_t)(bi * 8 + j) * 500 + 250;
    __shared__ float row[256];
    float s = 0.f, s2 = 0.f;
    for (int c = threadIdx.x; c < 250; c += 256) {
        float v = ar[c] + br[c] + bias[c];
        row[c] = v; s += v; s2 += v * v;
    }
    reduce2(s, s2);
    float mean = s / 250.f, var = s2 / 250.f - mean * mean, rsg = rsqrtf(var + EPSF);
    float* o = core + (size_t)r * 250;
    for (int c = threadIdx.x; c < 250; c += 256) {
        float v = (row[c] - mean) * rsg;
        o[c] = v > 0.f ? v : 0.f;
    }
}

// ---------------- fused: att1 split-K reduce + bias + LN + tanh-dot + sigmoid ----------------
__global__ void k_att2(const float* __restrict__ part, const float* __restrict__ b1,
                       const float* __restrict__ w2, const float* __restrict__ b2,
                       float* __restrict__ att, int M, int nsplit) {
    __shared__ float row[128];
    int r = blockIdx.x;
    float s = 0.f, s2 = 0.f;
    for (int c = threadIdx.x; c < 100; c += 256) {
        float v = b1[c];
        for (int z = 0; z < nsplit; z++) v += part[((size_t)z * M + r) * 100 + c];
        row[c] = v; s += v; s2 += v * v;
    }
    reduce2(s, s2);
    float mean = s / 100.f, var = s2 / 100.f - mean * mean, rsg = rsqrtf(var + EPSF);
    float d = 0.f;
    for (int c = threadIdx.x; c < 100; c += 256)
        d += tanhf((row[c] - mean) * rsg) * w2[c];
    float dummy = 0.f;
    reduce2(d, dummy);
    if (threadIdx.x == 0) att[r] = 1.f / (1.f + expf(-(d + b2[0])));
}

// ---------------- fused: effect + concat total = [s1, sum_jj ctx*att, hf] ----------------
__global__ void k_total2(const float* __restrict__ s1, const float* __restrict__ ctx,
                         const float* __restrict__ att, const float* __restrict__ hf,
                         float* __restrict__ total) {
    int idx = blockIdx.x * 256 + threadIdx.x;
    if (idx >= 384 * 1012) return;
    int n = idx / 1012, c = idx % 1012;
    float v;
    if (c < 250) v = s1[n * 250 + c];
    else if (c < 500) {
        int cc = c - 250;
        float s = 0.f;
        #pragma unroll
        for (int jj = 0; jj < 7; jj++)
            s += ctx[((size_t)n * 7 + jj) * 250 + cc] * att[n * 7 + jj];
        v = s;
    } else v = hf[n * 512 + (c - 500)];
    total[idx] = v;
}

// ---------------- fused: out-GEMM reduce + bias; xr = sigmoid(ln(ns)); so = sigmoid(ns) ----------------
__global__ void k_state2(const float* __restrict__ part, const float* __restrict__ bias,
                         float* __restrict__ xr, float* __restrict__ so, int nsplit) {
    __shared__ float row[256];
    int r = blockIdx.x;                  // M = 384, N = 250
    float s = 0.f, s2 = 0.f;
    for (int c = threadIdx.x; c < 250; c += 256) {
        float v = bias[c];
        for (int z = 0; z < nsplit; z++) v += part[((size_t)z * 384 + r) * 250 + c];
        row[c] = v; s += v; s2 += v * v;
    }
    reduce2(s, s2);
    float mean = s / 250.f, var = s2 / 250.f - mean * mean, rsg = rsqrtf(var + EPSF);
    for (int c = threadIdx.x; c < 250; c += 256) {
        float v = row[c];
        xr[(size_t)r * 250 + c] = 1.f / (1.f + expf(-((v - mean) * rsg)));
        so[(size_t)r * 250 + c] = 1.f / (1.f + expf(-v));
    }
}

// ---------------- launch ----------------
extern "C" void kernel_launch(void* const* d_in, const int* in_sizes, int n_in,
                              void* d_out, int out_size) {
    const float* x     = (const float*)d_in[0];
    const float* state = (const float*)d_in[1];
    const float* c1w   = (const float*)d_in[2];  const float* c1b  = (const float*)d_in[3];
    const float* c2w   = (const float*)d_in[4];  const float* c2b  = (const float*)d_in[5];
    const float* c3w   = (const float*)d_in[6];  const float* c3b  = (const float*)d_in[7];
    const float* efcw  = (const float*)d_in[8];  const float* efcb = (const float*)d_in[9];
    const float* rencw = (const float*)d_in[10]; const float* rencb= (const float*)d_in[11];
    const float* corew = (const float*)d_in[12]; const float* coreb= (const float*)d_in[13];
    const float* ctxw  = (const float*)d_in[14]; const float* ctxb = (const float*)d_in[15];
    const float* att1w = (const float*)d_in[16]; const float* att1b= (const float*)d_in[17];
    const float* att2w = (const float*)d_in[18]; const float* att2b= (const float*)d_in[19];
    const float* outw  = (const float*)d_in[20]; const float* outb = (const float*)d_in[21];
    const float* dfc1w = (const float*)d_in[22]; const float* dfc1b= (const float*)d_in[23];
    const float* dfc2w = (const float*)d_in[24]; const float* dfc2b= (const float*)d_in[25];
    const float* d1w   = (const float*)d_in[26]; const float* d1b  = (const float*)d_in[27];
    const float* d2w   = (const float*)d_in[28]; const float* d2b  = (const float*)d_in[29];
    const float* d3w   = (const float*)d_in[30]; const float* d3b  = (const float*)d_in[31];
    float* out = (float*)d_out;

    float* S = nullptr;
    cudaGetSymbolAddress((void**)&S, g_scratch);
    float* h1   = S;                    // 6291456
    float* h2   = h1  + 6291456;        // 3145728
    float* h3   = h2  + 3145728;        // 1572864
    float* hf   = h3  + 1572864;        // 196608
    float* s1   = hf  + 196608;         // 96000
    float* AB   = s1  + 96000;          // 192000
    float* core = AB  + 192000;         // 672000
    float* ctx  = core+ 672000;         // 672000
    float* att  = ctx + 672000;         // 2688
    float* tot  = att + 2688;           // 388608
    float* xr   = tot + 388608;         // 96000
    float* d1   = xr  + 96000;          // 196608
    float* d2   = d1  + 196608;         // 1572864
    float* dd1  = d2  + 1572864;        // 3145728
    float* dd2  = dd1 + 3145728;        // 6291456
    float* Bcat = dd2 + 6291456;        // 125000
    float* part = Bcat+ 125000;         // 1600000

    cudaFuncSetAttribute(k_conv_b<32,16,32,4>,    cudaFuncAttributeMaxDynamicSharedMemorySize, (16384+8192+32)*4);
    cudaFuncSetAttribute(k_conv_b<16,32,64,4>,    cudaFuncAttributeMaxDynamicSharedMemorySize, (8192+32768+64)*4);
    cudaFuncSetAttribute(k_deconv_b<8,64,32,4,0>, cudaFuncAttributeMaxDynamicSharedMemorySize, (4096+32768+32)*4);
    cudaFuncSetAttribute(k_deconv_b<16,32,16,4,0>,cudaFuncAttributeMaxDynamicSharedMemorySize, (8192+8192+16)*4);
    cudaFuncSetAttribute(k_deconv_b<32,16,1,8,1>, cudaFuncAttributeMaxDynamicSharedMemorySize, (16384+256+1)*4);

    const float* NOB = nullptr;

    // ---- encoder ----
    k_conv_b<64,1,16,4><<<384, 256, (4096+256+16)*4>>>(x, c1w, c1b, h1);
    k_conv_b<32,16,32,4><<<384, 256, (16384+8192+32)*4>>>(h1, c2w, c2b, h2);
    k_conv_b<16,32,64,4><<<384, 256, (8192+32768+64)*4>>>(h2, c3w, c3b, h3);
    { dim3 g(8, 6, 8); k_gemm2<<<g, 256>>>(h3, efcw, NOB, part, 384, 512, 4096, 32); }
    k_reduce_ln<<<384, 256>>>(part, efcb, hf, 384, 512, 8, 0);

    // ---- recurrent / pairwise ----
    { dim3 g(4, 6, 4); k_gemm2<<<g, 256>>>(state, rencw, NOB, part, 384, 250, 250, 4); }
    k_reduce_ln<<<384, 256>>>(part, rencb, s1, 384, 250, 4, 1);
    k_catW<<<(125000 + 255) / 256, 256>>>(corew, Bcat);
    { dim3 g(8, 6, 4); k_gemm2<<<g, 256>>>(s1, Bcat, NOB, part, 384, 500, 250, 4); }
    k_reduce_ln<<<384, 256>>>(part, NOB, AB, 384, 500, 4, -1);
    k_core<<<2688, 256>>>(AB, coreb, core);
    { dim3 g(4, 42, 2); k_gemm2<<<g, 256>>>(core, ctxw, NOB, part, 2688, 250, 250, 8); }
    k_reduce_ln<<<2688, 256>>>(part, ctxb, ctx, 2688, 250, 2, 1);
    { dim3 g(2, 42, 4); k_gemm2<<<g, 256>>>(core, att1w, NOB, part, 2688, 100, 250, 4); }
    k_att2<<<2688, 256>>>(part, att1b, att2w, att2b, att, 2688, 4);
    k_total2<<<(388608 + 255) / 256, 256>>>(s1, ctx, att, hf, tot);
    { dim3 g(4, 6, 8); k_gemm2<<<g, 256>>>(tot, outw, NOB, part, 384, 250, 1012, 8); }
    k_state2<<<384, 256>>>(part, outb, xr, out + 384 * 4096, 8);

    // ---- decoder ----
    { dim3 g(8, 6, 4); k_gemm2<<<g, 256>>>(xr, dfc1w, NOB, part, 384, 512, 250, 4); }
    k_reduce_ln<<<384, 256>>>(part, dfc1b, d1, 384, 512, 4, 1);
    { dim3 g(64, 6, 1); k_gemm2<<<g, 256>>>(d1, dfc2w, dfc2b, d2, 384, 4096, 512, 32); }
    k_ln_act<<<384, 256>>>(d2, 4096, 1);
    k_deconv_b<8,64,32,4,0><<<384, 256, (4096+32768+32)*4>>>(d2, d1w, d1b, dd1);
    k_deconv_b<16,32,16,4,0><<<384, 256, (8192+8192+16)*4>>>(dd1, d2w, d2b, dd2);
    k_deconv_b<32,16,1,8,1><<<384, 256, (16384+256+1)*4>>>(dd2, d3w, d3b, out);
}